// round 3
// baseline (speedup 1.0000x reference)
#include <cuda_runtime.h>
#include <cuda_bf16.h>

// Problem shape (fixed by the reference):
//   z        : [B=8, N=64, M=512, F=256] f32      (67,108,864 elems)
//   Mask     : [B=8, F=256] int in [0,15)          (2,048 elems; dtype detected at runtime)
//   eta_fault: [15, 4] f32                         (60 elems)
//   out[b,n,m,f] = e0 + e1 * sigmoid((z - e2) * e3),  e = eta_fault[Mask[b,f]]
//
// sigmoid(x) = 0.5 + 0.5*tanh(0.5*x)  -> single MUFU.TANH per element.
// Folded per-(b,f):  s=0.5*e1 ; a=e0+s ; m=0.5*e3 ; d=e2*m
//   out = fma(s, tanh(fma(z, m, -d)), a)

#define B_DIM 8
#define N_DIM 64
#define M_DIM 512
#define F_DIM 256
#define N_ETA 15

constexpr int NBF           = B_DIM * F_DIM;             // 2048 (b,f) pairs
constexpr int ROWS_PER_B    = N_DIM * M_DIM;             // 32768 rows of 256 floats
constexpr int F4            = F_DIM / 4;                 // 64 float4 per row
constexpr int THREADS       = 256;
constexpr int ROWS_PER_ITER = THREADS / F4;              // 4
constexpr int BLOCKS_PER_B  = 256;
constexpr int ROWS_PER_BLK  = ROWS_PER_B / BLOCKS_PER_B; // 128
constexpr int ITERS         = ROWS_PER_BLK / ROWS_PER_ITER; // 32

// Folded coefficients per (b,f): (s, a, m, d)
__device__ float4 g_coef[NBF];

__device__ __forceinline__ float tanh_ap(float x) {
    float r;
    asm("tanh.approx.f32 %0, %1;" : "=f"(r) : "f"(x));
    return r;
}

// Prologue: detect Mask dtype (int32 vs int64), gather eta, fold constants.
// Launched <<<1, 1024>>>. Reading 1024 int64s is safe for both dtypes
// (int32 buffer: 2048*4B = 8KB = exactly 1024 int64s).
__global__ void prep_kernel(const void* __restrict__ mask_raw,
                            const float* __restrict__ eta)
{
    __shared__ int bad;
    if (threadIdx.x == 0) bad = 0;
    __syncthreads();

    const long long* m64 = (const long long*)mask_raw;
    long long probe = m64[threadIdx.x];
    if (probe < 0 || probe >= N_ETA) atomicOr(&bad, 1);
    __syncthreads();
    const bool is64 = (bad == 0);

    const int* m32 = (const int*)mask_raw;
    for (int k = threadIdx.x; k < NBF; k += 1024) {
        int idx = is64 ? (int)m64[k] : m32[k];
        idx = max(0, min(N_ETA - 1, idx));   // crash-proof under any dtype
        float e0 = eta[idx * 4 + 0];
        float e1 = eta[idx * 4 + 1];
        float e2 = eta[idx * 4 + 2];
        float e3 = eta[idx * 4 + 3];
        float s = 0.5f * e1;
        float m = 0.5f * e3;
        g_coef[k] = make_float4(s, e0 + s, m, e2 * m);
    }
}

__global__ __launch_bounds__(THREADS) void sigmoid_rt_kernel(
    const float4* __restrict__ z,
    float4* __restrict__ out)
{
    const int b    = blockIdx.x / BLOCKS_PER_B;
    const int blk  = blockIdx.x % BLOCKS_PER_B;
    const int fi   = threadIdx.x & (F4 - 1);   // float4 column (fixed per thread)
    const int rsub = threadIdx.x >> 6;         // row within the 4-row group

    // This thread's 4 coefficient quads, loaded once.
    float4 c[4];
#pragma unroll
    for (int j = 0; j < 4; ++j)
        c[j] = g_coef[b * F_DIM + 4 * fi + j];

    const long base_row = (long)b * ROWS_PER_B + (long)blk * ROWS_PER_BLK + rsub;
    const float4* zp = z   + base_row * F4 + fi;
    float4*       op = out + base_row * F4 + fi;
    const long stride = (long)ROWS_PER_ITER * F4;   // 256 float4 per step

#pragma unroll 4
    for (int it = 0; it < ITERS; ++it) {
        float4 v = zp[it * stride];
        float4 r;
        r.x = fmaf(c[0].x, tanh_ap(fmaf(v.x, c[0].z, -c[0].w)), c[0].y);
        r.y = fmaf(c[1].x, tanh_ap(fmaf(v.y, c[1].z, -c[1].w)), c[1].y);
        r.z = fmaf(c[2].x, tanh_ap(fmaf(v.z, c[2].z, -c[2].w)), c[2].y);
        r.w = fmaf(c[3].x, tanh_ap(fmaf(v.w, c[3].z, -c[3].w)), c[3].y);
        op[it * stride] = r;
    }
}

extern "C" void kernel_launch(void* const* d_in, const int* in_sizes, int n_in,
                              void* d_out, int out_size)
{
    // Bind inputs by element count — robust to metadata ordering.
    //   z = 67,108,864 ; Mask = 2,048 ; eta_fault = 60
    const void*  mask = nullptr;
    const float* eta  = nullptr;
    const float4* z   = nullptr;
    for (int i = 0; i < n_in; ++i) {
        if (in_sizes[i] > 1000000)          z    = (const float4*)d_in[i];
        else if (in_sizes[i] == NBF)        mask = d_in[i];
        else                                 eta  = (const float*)d_in[i];
    }

    prep_kernel<<<1, 1024>>>(mask, eta);
    sigmoid_rt_kernel<<<B_DIM * BLOCKS_PER_B, THREADS>>>(z, (float4*)d_out);
}